// round 17
// baseline (speedup 1.0000x reference)
#include <cuda_runtime.h>
#include <cuda_fp16.h>
#include <cstdint>

#define Bsz   2048
#define Lseq  256

// ---------------- device scratch ----------------
__device__ float g_T0[2 * 128 * 256];                 // token table [dir][tok][cell][gate4] fp32
__device__ __half g_y0[(size_t)Lseq * Bsz * 128];     // layer-0 output fp16 [t][b][128]
__device__ float g_hfin[Bsz * 128];                   // layer-1 final hidden [b][hf|hb]

// ---------------- helpers ----------------
__device__ __forceinline__ uint32_t s2u(const void* p) {
    uint32_t a;
    asm("{ .reg .u64 t; cvta.to.shared.u64 t, %1; cvt.u32.u64 %0, t; }" : "=r"(a) : "l"(p));
    return a;
}
__device__ __forceinline__ float tanha(float x) {
    float y; asm("tanh.approx.f32 %0, %1;" : "=f"(y) : "f"(x)); return y;
}
__device__ __forceinline__ float sigf(float x) { return fmaf(0.5f, tanha(0.5f * x), 0.5f); }

__device__ __forceinline__ void ldsm4(uint32_t* r, uint32_t addr) {
    asm volatile("ldmatrix.sync.aligned.m8n8.x4.shared.b16 {%0,%1,%2,%3}, [%4];"
        : "=r"(r[0]), "=r"(r[1]), "=r"(r[2]), "=r"(r[3]) : "r"(addr));
}
__device__ __forceinline__ void mmaf16(float* d, const uint32_t* a, const uint32_t* b) {
    asm volatile("mma.sync.aligned.m16n8k16.row.col.f32.f16.f16.f32 "
        "{%0,%1,%2,%3}, {%4,%5,%6,%7}, {%8,%9}, {%0,%1,%2,%3};"
        : "+f"(d[0]), "+f"(d[1]), "+f"(d[2]), "+f"(d[3])
        : "r"(a[0]), "r"(a[1]), "r"(a[2]), "r"(a[3]), "r"(b[0]), "r"(b[1]));
}
__device__ __forceinline__ void split2h(float v, __half& hi, __half& lo) {
    hi = __float2half_rn(v);
    lo = __float2half_rn(v - __half2float(hi));
}

// ================= kernel 1: layer-0 token table (fp32 exact) =================
__global__ void table_kernel(const float* __restrict__ emb,
                             const float* __restrict__ Wih0,
                             const float* __restrict__ b0) {
    const int v = blockIdx.x, dir = blockIdx.y, tid = threadIdx.x;
    const int cell = tid >> 2, gate = tid & 3;
    __shared__ float se[64];
    if (tid < 64) se[tid] = emb[v * 64 + tid];
    __syncthreads();
    const float* wrow = Wih0 + (size_t)(dir * 256 + gate * 64 + cell) * 64;
    float s = b0[dir * 512 + gate * 64 + cell] + b0[dir * 512 + 256 + gate * 64 + cell];
#pragma unroll
    for (int k = 0; k < 64; k++) s += se[k] * wrow[k];
    g_T0[((size_t)(dir * 128 + v) * 64 + cell) * 4 + gate] = s;
}

// ================= kernel 2: layer-0 LSTM (unchanged; proven r13-r16) =================
__global__ void __launch_bounds__(256, 2)
lstm0_kernel(const int* __restrict__ xtok, const float* __restrict__ Whh0) {
    constexpr int SA  = 144;
    constexpr int ALO = 256 * SA;
    constexpr int BH0 = 2 * 256 * SA;
    constexpr int BH1 = BH0 + 16 * SA;
    extern __shared__ __align__(16) char smem[];
    const uint32_t sb = s2u(smem);
    const int dir = blockIdx.y, b0i = blockIdx.x * 16;
    const int tid = threadIdx.x, lane = tid & 31, w = tid >> 5;

    {
        const int m = tid;
        const int cellm = 8 * (m >> 5) + (m & 7), gate = (m >> 3) & 3;
        const float* sh = Whh0 + (size_t)(dir * 256 + gate * 64 + cellm) * 64;
        char* rowp = smem + m * SA;
#pragma unroll 8
        for (int k = 0; k < 64; k++) {
            __half hi, lo; split2h(sh[k], hi, lo);
            *(__half*)(rowp + k * 2) = hi;
            *(__half*)(rowp + ALO + k * 2) = lo;
        }
    }
    if (tid < 128) {
        int row = tid >> 3, ch = tid & 7;
        *(uint4*)(smem + BH0 + row * SA + ch * 16) = make_uint4(0, 0, 0, 0);
    }
    __syncthreads();

    const int lrow = ((lane >> 3) & 1) * 8 + (lane & 7);
    const int lk8 = lane >> 4;
    const uint32_t a_base = sb + (32 * w + lrow) * SA + lk8 * 16;
    const uint32_t alo_base = a_base + ALO;
    uint32_t ahi0[4][4], ahi1[4][4];
#pragma unroll
    for (int kt = 0; kt < 4; kt++) {
        ldsm4(ahi0[kt], a_base + kt * 32);
        ldsm4(ahi1[kt], a_base + 16 * SA + kt * 32);
    }
    const int bn = 8 * (lane >> 4) + (lane & 7), bk8 = (lane >> 3) & 1;
    const uint32_t bh_base0 = sb + BH0 + bn * SA + bk8 * 16;
    const uint32_t bh_base1 = sb + BH1 + bn * SA + bk8 * 16;

    const int cell = 8 * w + (lane >> 2);
    float cs[2][2];
    cs[0][0] = cs[0][1] = cs[1][0] = cs[1][1] = 0.f;
    const int srow = (tid >> 3) & 15, sch = tid & 7;
    const float* T0 = g_T0 + (size_t)dir * 128 * 256;

    for (int t = 0; t < Lseq; t++) {
        const int tcur = dir ? (Lseq - 1 - t) : t;
        const uint32_t bh_cur = (t & 1) ? bh_base1 : bh_base0;
        const uint32_t bwofs  = (t & 1) ? BH0 : BH1;

        if (t > 0 && tid < 128) {
            int tprev = dir ? (Lseq - t) : (t - 1);
            uint32_t rofs = ((t & 1) ? BH1 : BH0) + srow * SA + sch * 16;
            *(uint4*)(g_y0 + ((size_t)tprev * Bsz + b0i + srow) * 128 + dir * 64 + sch * 8)
                = *(uint4*)(smem + rofs);
        }

        float4 tv[2][2];
#pragma unroll
        for (int nt = 0; nt < 2; nt++)
#pragma unroll
            for (int hh = 0; hh < 2; hh++) {
                int bb = 8 * nt + 2 * (lane & 3) + hh;
                int tok = __ldg(&xtok[(b0i + bb) * Lseq + tcur]);
                tv[nt][hh] = *(const float4*)(T0 + ((size_t)tok * 64 + cell) * 4);
            }

        float acc[2][2][4];
#pragma unroll
        for (int mt = 0; mt < 2; mt++)
#pragma unroll
            for (int nt = 0; nt < 2; nt++)
#pragma unroll
                for (int r = 0; r < 4; r++) acc[mt][nt][r] = 0.f;
#pragma unroll
        for (int kt = 0; kt < 4; kt++) {
            uint32_t alo0[4], alo1[4], bh0[4];
            ldsm4(alo0, alo_base + kt * 32);
            ldsm4(alo1, alo_base + 16 * SA + kt * 32);
            ldsm4(bh0, bh_cur + kt * 32);
            mmaf16(acc[0][0], ahi0[kt], bh0);     mmaf16(acc[0][0], alo0, bh0);
            mmaf16(acc[0][1], ahi0[kt], bh0 + 2); mmaf16(acc[0][1], alo0, bh0 + 2);
            mmaf16(acc[1][0], ahi1[kt], bh0);     mmaf16(acc[1][0], alo1, bh0);
            mmaf16(acc[1][1], ahi1[kt], bh0 + 2); mmaf16(acc[1][1], alo1, bh0 + 2);
        }

#pragma unroll
        for (int nt = 0; nt < 2; nt++)
#pragma unroll
            for (int hh = 0; hh < 2; hh++) {
                float iv = acc[0][nt][hh]     + tv[nt][hh].x;
                float fv = acc[0][nt][2 + hh] + tv[nt][hh].y;
                float gv = acc[1][nt][hh]     + tv[nt][hh].z;
                float ov = acc[1][nt][2 + hh] + tv[nt][hh].w;
                float c = sigf(fv) * cs[nt][hh] + sigf(iv) * tanha(gv);
                cs[nt][hh] = c;
                float h = sigf(ov) * tanha(c);
                int bb = 8 * nt + 2 * (lane & 3) + hh;
                *(__half*)(smem + bwofs + bb * SA + cell * 2) = __float2half_rn(h);
            }
        __syncthreads();
    }
    if (tid < 128) {
        int tprev = dir ? 0 : (Lseq - 1);
        *(uint4*)(g_y0 + ((size_t)tprev * Bsz + b0i + srow) * 128 + dir * 64 + sch * 8)
            = *(uint4*)(smem + BH0 + srow * SA + sch * 16);
    }
}

// ================= kernel 3: layer-1 LSTM =================
// NB=32, weights fp16 hi-only, dual accumulator (r15). NEW: the epilogue(t) is
// hand-INTERLEAVED chunk-by-chunk with the x-mma(t+1) kt-blocks so MUFU issues
// fill the 8-cyc gaps between in-order HMMA issues of the SAME warp.
#define LSTM1_ZACC(A)                                                          \
    do {                                                                       \
        _Pragma("unroll")                                                      \
        for (int mt = 0; mt < 2; mt++)                                         \
            _Pragma("unroll")                                                  \
            for (int nt = 0; nt < 4; nt++)                                     \
                _Pragma("unroll")                                              \
                for (int r = 0; r < 4; r++) A[mt][nt][r] = 0.f;                \
    } while (0)

#define LSTM1_HMMA(A, BHCUR)                                                   \
    do {                                                                       \
        _Pragma("unroll")                                                      \
        for (int kh = 0; kh < 4; kh++) {                                       \
            uint32_t bh0[4], bh1[4];                                           \
            ldsm4(bh0, (BHCUR) + kh * 32);                                     \
            ldsm4(bh1, (BHCUR) + 16 * SH + kh * 32);                           \
            mmaf16(A[0][0], ahi0[8 + kh], bh0);                                \
            mmaf16(A[0][1], ahi0[8 + kh], bh0 + 2);                            \
            mmaf16(A[0][2], ahi0[8 + kh], bh1);                                \
            mmaf16(A[0][3], ahi0[8 + kh], bh1 + 2);                            \
            mmaf16(A[1][0], ahi1[8 + kh], bh0);                                \
            mmaf16(A[1][1], ahi1[8 + kh], bh0 + 2);                            \
            mmaf16(A[1][2], ahi1[8 + kh], bh1);                                \
            mmaf16(A[1][3], ahi1[8 + kh], bh1 + 2);                            \
        }                                                                      \
    } while (0)

// one kt-block of x-mma(t+1) into A (8 HMMA + 2 LDSM)
#define XMMA_KT(A, BXCUR, KT)                                                  \
    do {                                                                       \
        uint32_t bx0[4], bx1[4];                                               \
        ldsm4(bx0, (BXCUR) + (KT) * 32);                                       \
        ldsm4(bx1, (BXCUR) + 16 * SX + (KT) * 32);                             \
        mmaf16(A[0][0], ahi0[KT], bx0);                                        \
        mmaf16(A[0][1], ahi0[KT], bx0 + 2);                                    \
        mmaf16(A[0][2], ahi0[KT], bx1);                                        \
        mmaf16(A[0][3], ahi0[KT], bx1 + 2);                                    \
        mmaf16(A[1][0], ahi1[KT], bx0);                                        \
        mmaf16(A[1][1], ahi1[KT], bx0 + 2);                                    \
        mmaf16(A[1][2], ahi1[KT], bx1);                                        \
        mmaf16(A[1][3], ahi1[KT], bx1 + 2);                                    \
    } while (0)

// one epilogue chunk: gates of (NT,HH) for this thread's 2 batch-cols
#define EPI_CHUNK(A, T, BHW, NT, HH)                                           \
    do {                                                                       \
        int bb = 8 * (NT) + 2 * (lane & 3) + (HH);                             \
        float iv = A[0][NT][HH]       + bi_;                                   \
        float fv = A[0][NT][2 + (HH)] + bf_;                                   \
        float gv = A[1][NT][HH]       + bg_;                                   \
        float ov = A[1][NT][2 + (HH)] + bo_;                                   \
        float c = sigf(fv) * cs[NT][HH] + sigf(iv) * tanha(gv);                \
        cs[NT][HH] = c;                                                        \
        float h = sigf(ov) * tanha(c);                                         \
        *(__half*)(smem + (BHW) + bb * SH + cell * 2) = __float2half_rn(h);    \
        if ((T) == Lseq - 1)                                                   \
            g_hfin[(b0i + bb) * 128 + dir * 64 + cell] = h;                    \
    } while (0)

// interleaved tail: x-mma(t+1) kt-blocks alternated with epilogue(t) chunks
#define TAIL_ILV(ACC_C, ACC_N, T, BHW, BXN, DOX)                               \
    do {                                                                       \
        if (DOX) XMMA_KT(ACC_N, BXN, 0);  EPI_CHUNK(ACC_C, T, BHW, 0, 0);      \
        if (DOX) XMMA_KT(ACC_N, BXN, 1);  EPI_CHUNK(ACC_C, T, BHW, 0, 1);      \
        if (DOX) XMMA_KT(ACC_N, BXN, 2);  EPI_CHUNK(ACC_C, T, BHW, 1, 0);      \
        if (DOX) XMMA_KT(ACC_N, BXN, 3);  EPI_CHUNK(ACC_C, T, BHW, 1, 1);      \
        if (DOX) XMMA_KT(ACC_N, BXN, 4);  EPI_CHUNK(ACC_C, T, BHW, 2, 0);      \
        if (DOX) XMMA_KT(ACC_N, BXN, 5);  EPI_CHUNK(ACC_C, T, BHW, 2, 1);      \
        if (DOX) XMMA_KT(ACC_N, BXN, 6);  EPI_CHUNK(ACC_C, T, BHW, 3, 0);      \
        if (DOX) XMMA_KT(ACC_N, BXN, 7);  EPI_CHUNK(ACC_C, T, BHW, 3, 1);      \
    } while (0)

__global__ void __launch_bounds__(256, 1)
lstm1_kernel(const float* __restrict__ Wih1, const float* __restrict__ Whh1,
             const float* __restrict__ bias) {
    constexpr int SAW = 400;                  // A row stride (192*2+16)
    constexpr int SH  = 144;                  // h row stride
    constexpr int SX  = 272;                  // x row stride
    constexpr int BX0 = 256 * SAW;            // 102400
    constexpr int BX1 = BX0 + 32 * SX;        // 111104
    constexpr int BH0 = BX1 + 32 * SX;        // 119808
    constexpr int BH1 = BH0 + 32 * SH;        // 124416 (total 129024)

    extern __shared__ __align__(16) char smem[];
    const uint32_t sb = s2u(smem);
    const int dir = blockIdx.y, b0i = blockIdx.x * 32;
    const int tid = threadIdx.x, lane = tid & 31, w = tid >> 5;

    // fill weights (hi only), permuted rows
    {
        const int m = tid;
        const int cellm = 8 * (m >> 5) + (m & 7), gate = (m >> 3) & 3;
        const int grow = dir * 256 + gate * 64 + cellm;
        const float* si = Wih1 + (size_t)grow * 128;
        const float* sh = Whh1 + (size_t)grow * 64;
        char* rowp = smem + m * SAW;
        for (int k = 0; k < 128; k++)
            *(__half*)(rowp + k * 2) = __float2half_rn(si[k]);
#pragma unroll 8
        for (int k = 0; k < 64; k++)
            *(__half*)(rowp + (128 + k) * 2) = __float2half_rn(sh[k]);
    }
    { // zero h buffer 0
        int row = tid >> 3, ch = tid & 7;
        *(uint4*)(smem + BH0 + row * SH + ch * 16) = make_uint4(0, 0, 0, 0);
    }
    // stage x(0) -> BX0, x(1) -> BX1
    const int r0 = tid >> 4, c0 = tid & 15, r1 = r0 + 16;
    {
        int t0n = dir ? (Lseq - 1) : 0;
        int t1n = dir ? (Lseq - 2) : 1;
        *(uint4*)(smem + BX0 + r0 * SX + c0 * 16)
            = *(const uint4*)(g_y0 + ((size_t)t0n * Bsz + b0i + r0) * 128 + c0 * 8);
        *(uint4*)(smem + BX0 + r1 * SX + c0 * 16)
            = *(const uint4*)(g_y0 + ((size_t)t0n * Bsz + b0i + r1) * 128 + c0 * 8);
        *(uint4*)(smem + BX1 + r0 * SX + c0 * 16)
            = *(const uint4*)(g_y0 + ((size_t)t1n * Bsz + b0i + r0) * 128 + c0 * 8);
        *(uint4*)(smem + BX1 + r1 * SX + c0 * 16)
            = *(const uint4*)(g_y0 + ((size_t)t1n * Bsz + b0i + r1) * 128 + c0 * 8);
    }
    __syncthreads();

    // A fragments -> registers (12 kt covering K=192)
    const int lrow = ((lane >> 3) & 1) * 8 + (lane & 7);
    const int lk8  = lane >> 4;
    const uint32_t a_base = sb + (32 * w + lrow) * SAW + lk8 * 16;
    uint32_t ahi0[12][4], ahi1[12][4];
#pragma unroll
    for (int kt = 0; kt < 12; kt++) {
        ldsm4(ahi0[kt], a_base + kt * 32);
        ldsm4(ahi1[kt], a_base + 16 * SAW + kt * 32);
    }
    const int bn  = 8 * (lane >> 4) + (lane & 7);
    const int bk8 = (lane >> 3) & 1;
    const uint32_t bxf0 = sb + BX0 + bn * SX + bk8 * 16;
    const uint32_t bxf1 = sb + BX1 + bn * SX + bk8 * 16;
    const uint32_t bhf0 = sb + BH0 + bn * SH + bk8 * 16;
    const uint32_t bhf1 = sb + BH1 + bn * SH + bk8 * 16;

    const int cell = 8 * w + (lane >> 2);
    const float* bp = bias + dir * 512;
    const float bi_ = bp[cell]       + bp[256 + cell];
    const float bf_ = bp[64 + cell]  + bp[320 + cell];
    const float bg_ = bp[128 + cell] + bp[384 + cell];
    const float bo_ = bp[192 + cell] + bp[448 + cell];

    float cs[4][2];
#pragma unroll
    for (int nt = 0; nt < 4; nt++) { cs[nt][0] = 0.f; cs[nt][1] = 0.f; }

    float accA[2][4][4], accB[2][4][4];
    LSTM1_ZACC(accA);
#pragma unroll
    for (int kt = 0; kt < 8; kt++) XMMA_KT(accA, bxf0, kt);   // x-part of step 0

    for (int t = 0; t < Lseq; t += 2) {
        // ---------- step t (even): cur=accA, next=accB ----------
        LSTM1_HMMA(accA, bhf0);                 // h(t-1) in BH0
        LSTM1_ZACC(accB);
        uint4 pf0, pf1;
        const bool hp = (t + 2 < Lseq);
        if (hp) {
            int tn = dir ? (Lseq - 3 - t) : (t + 2);
            pf0 = *(const uint4*)(g_y0 + ((size_t)tn * Bsz + b0i + r0) * 128 + c0 * 8);
            pf1 = *(const uint4*)(g_y0 + ((size_t)tn * Bsz + b0i + r1) * 128 + c0 * 8);
        }
        TAIL_ILV(accA, accB, t, BH1, bxf1, true);   // x-mma(t+1) ∥ epilogue(t)
        if (hp) {
            *(uint4*)(smem + BX0 + r0 * SX + c0 * 16) = pf0;   // x(t+2) -> BX0
            *(uint4*)(smem + BX0 + r1 * SX + c0 * 16) = pf1;
        }
        __syncthreads();

        // ---------- step t+1 (odd): cur=accB, next=accA ----------
        LSTM1_HMMA(accB, bhf1);                 // h(t) in BH1
        LSTM1_ZACC(accA);
        uint4 qf0, qf1;
        const bool hq = (t + 3 < Lseq);
        if (hq) {
            int tn = dir ? (Lseq - 4 - t) : (t + 3);
            qf0 = *(const uint4*)(g_y0 + ((size_t)tn * Bsz + b0i + r0) * 128 + c0 * 8);
            qf1 = *(const uint4*)(g_y0 + ((size_t)tn * Bsz + b0i + r1) * 128 + c0 * 8);
        }
        TAIL_ILV(accB, accA, t + 1, BH0, bxf0, hp); // x-mma(t+2) ∥ epilogue(t+1)
        if (hq) {
            *(uint4*)(smem + BX1 + r0 * SX + c0 * 16) = qf0;   // x(t+3) -> BX1
            *(uint4*)(smem + BX1 + r1 * SX + c0 * 16) = qf1;
        }
        __syncthreads();
    }
}

// ================= kernel 4: MLP head =================
__global__ void __launch_bounds__(256)
head_kernel(const float* __restrict__ W1, const float* __restrict__ bf1,
            const float* __restrict__ W2, const float* __restrict__ bf2,
            float* __restrict__ out) {
    extern __shared__ float hs[];
    float* sW1 = hs;                           // [64][129]
    float* sh  = hs + 64 * 129;                // [32][129]
    float* sW2 = hs + 64 * 129 + 32 * 129;     // [64]
    float* sb1 = sW2 + 64;                     // [64]
    const int tid = threadIdx.x;
    const int b0 = blockIdx.x * 32;

    for (int i = tid; i < 64 * 128; i += 256) sW1[(i >> 7) * 129 + (i & 127)] = W1[i];
    for (int i = tid; i < 32 * 128; i += 256) sh[(i >> 7) * 129 + (i & 127)] = g_hfin[b0 * 128 + i];
    if (tid < 64) { sW2[tid] = W2[tid]; sb1[tid] = bf1[tid]; }
    __syncthreads();

    const int bi = tid >> 3, g8 = tid & 7;
    const float* hrow = sh + bi * 129;
    float part = 0.f;
#pragma unroll
    for (int jj = 0; jj < 8; jj++) {
        int j = g8 * 8 + jj;
        float z = sb1[j];
        const float* wrow = sW1 + j * 129;
#pragma unroll 16
        for (int k = 0; k < 128; k++) z += hrow[k] * wrow[k];
        part += fmaxf(z, 0.f) * sW2[j];
    }
#pragma unroll
    for (int o = 4; o; o >>= 1) part += __shfl_down_sync(0xffffffffu, part, o, 8);
    if (g8 == 0) out[b0 + bi] = part + bf2[0];
}

// ================= launch =================
extern "C" void kernel_launch(void* const* d_in, const int* in_sizes, int n_in,
                              void* d_out, int out_size) {
    const int*   x    = (const int*)  d_in[0];
    const float* emb  = (const float*)d_in[1];
    const float* Wih0 = (const float*)d_in[2];
    const float* Whh0 = (const float*)d_in[3];
    const float* b0   = (const float*)d_in[4];
    const float* Wih1 = (const float*)d_in[5];
    const float* Whh1 = (const float*)d_in[6];
    const float* b1   = (const float*)d_in[7];
    const float* W1   = (const float*)d_in[8];
    const float* bf1  = (const float*)d_in[9];
    const float* W2   = (const float*)d_in[10];
    const float* bf2  = (const float*)d_in[11];
    float* out = (float*)d_out;

    const int SM0 = 2 * 256 * 144 + 2 * 16 * 144;                 // 78336
    const int SM1 = 256 * 400 + 2 * 32 * 272 + 2 * 32 * 144;      // 129024
    const int SMH = (64 * 129 + 32 * 129 + 128) * 4;
    cudaFuncSetAttribute(lstm0_kernel, cudaFuncAttributeMaxDynamicSharedMemorySize, SM0);
    cudaFuncSetAttribute(lstm1_kernel, cudaFuncAttributeMaxDynamicSharedMemorySize, SM1);
    cudaFuncSetAttribute(head_kernel,  cudaFuncAttributeMaxDynamicSharedMemorySize, SMH);

    table_kernel<<<dim3(128, 2), 256>>>(emb, Wih0, b0);
    lstm0_kernel<<<dim3(Bsz / 16, 2), 256, SM0>>>(x, Whh0);
    lstm1_kernel<<<dim3(Bsz / 32, 2), 256, SM1>>>(Wih1, Whh1, b1);
    head_kernel<<<64, 256, SMH>>>(W1, bf1, W2, bf2, out);
}